// round 15
// baseline (speedup 1.0000x reference)
#include <cuda_runtime.h>
#include <cuda_bf16.h>
#include <cuda_fp16.h>
#include <cstdint>
#include <cstddef>

// ---------------------------------------------------------------------------
// Problem constants
// ---------------------------------------------------------------------------
#define B_     4
#define N_     2048
#define QD     1024
#define H_     16
#define DH     64
#define INNER_ 1024
#define BH     (B_ * H_)     // 64
#define ROWS   (B_ * N_)     // 8192

// Smem tile geometry
#define PITCH   144                     // 64-col 16-bit tiles (128B data)
#define TILE_A  (128 * PITCH)           // 18432
#define TILE_K64 (64 * PITCH)           // 9216
#define STG_GEMM (4 * TILE_A)           // 73728 per stage (qkv)
#define SM_QKV   (2 * STG_GEMM)         // 147456, 1 CTA/SM
#define SM_OUT   (4 * TILE_A)           // 73728 single-buffer (outproj, 2 CTA)

// Fused attention smem layout (key-block = 64, KV double-buffered)
#define OFF_QH   0
#define OFF_QL   (OFF_QH + TILE_A)          // Q: 128x64 hi/lo
#define OFF_KV   (OFF_QL + TILE_A)          // 2 stages of (Kh,Kl,V) 64x64
#define STG_KV   (3 * TILE_K64)             // 27648
#define OFF_P    (OFF_KV + 2 * STG_KV)      // P: 128x64 fp16
#define SM_FUSED (OFF_P + TILE_A)           // 110592 -> 2 CTAs/SM

// ---------------------------------------------------------------------------
// Device scratch (allocation-free)
// ---------------------------------------------------------------------------
__device__ __nv_bfloat16 g_xh[(size_t)ROWS * QD];
__device__ __nv_bfloat16 g_xl[(size_t)ROWS * QD];
__device__ __nv_bfloat16 g_wth[(size_t)4 * QD * INNER_];   // [slot][n][k]
__device__ __nv_bfloat16 g_wtl[(size_t)4 * QD * INNER_];
__device__ __nv_bfloat16 g_qh[(size_t)BH * N_ * DH];
__device__ __nv_bfloat16 g_ql[(size_t)BH * N_ * DH];
__device__ __nv_bfloat16 g_kh[(size_t)BH * N_ * DH];
__device__ __nv_bfloat16 g_kl[(size_t)BH * N_ * DH];
__device__ __half        g_vt[(size_t)BH * DH * N_];       // [bh][d][n] fp16
__device__ __nv_bfloat16 g_ath[(size_t)ROWS * INNER_];
__device__ __nv_bfloat16 g_atl[(size_t)ROWS * INNER_];
__device__ uint32_t      g_mb[(size_t)B_ * N_ * (N_ / 32)];

// ---------------------------------------------------------------------------
// Helpers
// ---------------------------------------------------------------------------
__device__ __forceinline__ uint32_t smem_to_u32(const void* p) {
    uint32_t a;
    asm("{ .reg .u64 t; cvta.to.shared.u64 t, %1; cvt.u32.u64 %0, t; }"
        : "=r"(a) : "l"(p));
    return a;
}

__device__ __forceinline__ void bsplit(float f, __nv_bfloat16& h, __nv_bfloat16& l) {
    h = __float2bfloat16(f);
    l = __float2bfloat16(f - __bfloat162float(h));
}

template <int PIT>
__device__ __forceinline__ void ldm_x4(uint32_t (&r)[4], uint32_t base, int row0,
                                       int ch0, int lane) {
    int m   = lane >> 3;
    int row = row0 + ((m & 1) << 3) + (lane & 7);
    int ch  = ch0 + (m >> 1);
    uint32_t addr = base + row * PIT + ch * 16;
    asm volatile("ldmatrix.sync.aligned.m8n8.x4.shared.b16 {%0,%1,%2,%3}, [%4];"
                 : "=r"(r[0]), "=r"(r[1]), "=r"(r[2]), "=r"(r[3]) : "r"(addr));
}

__device__ __forceinline__ void mma_bf16(float (&d)[4], const uint32_t (&a)[4],
                                         uint32_t b0, uint32_t b1) {
    asm volatile(
        "mma.sync.aligned.m16n8k16.row.col.f32.bf16.bf16.f32 "
        "{%0,%1,%2,%3}, {%4,%5,%6,%7}, {%8,%9}, {%0,%1,%2,%3};"
        : "+f"(d[0]), "+f"(d[1]), "+f"(d[2]), "+f"(d[3])
        : "r"(a[0]), "r"(a[1]), "r"(a[2]), "r"(a[3]), "r"(b0), "r"(b1));
}

__device__ __forceinline__ void mma_f16(float (&d)[4], const uint32_t (&a)[4],
                                        uint32_t b0, uint32_t b1) {
    asm volatile(
        "mma.sync.aligned.m16n8k16.row.col.f32.f16.f16.f32 "
        "{%0,%1,%2,%3}, {%4,%5,%6,%7}, {%8,%9}, {%0,%1,%2,%3};"
        : "+f"(d[0]), "+f"(d[1]), "+f"(d[2]), "+f"(d[3])
        : "r"(a[0]), "r"(a[1]), "r"(a[2]), "r"(a[3]), "r"(b0), "r"(b1));
}

// ---- GEMM chunk staging (BK=64, 4 tiles of 128 rows) -----------------------
struct ChunkRegs {
    uint4 vAh[4], vAl[4], vBh[4], vBl[4];
};

__device__ __forceinline__ void ldg_chunk64(
    ChunkRegs& cr,
    const __nv_bfloat16* gAh, const __nv_bfloat16* gAl,
    const __nv_bfloat16* gBh, const __nv_bfloat16* gBl,
    size_t ldA, size_t ldB, int tid)
{
#pragma unroll
    for (int j = 0; j < 4; j++) {
        int i = tid + j * 256, r = i >> 3, c = i & 7;
        cr.vAh[j] = *((const uint4*)(gAh + (size_t)r * ldA) + c);
        cr.vAl[j] = *((const uint4*)(gAl + (size_t)r * ldA) + c);
        cr.vBh[j] = *((const uint4*)(gBh + (size_t)r * ldB) + c);
        cr.vBl[j] = *((const uint4*)(gBl + (size_t)r * ldB) + c);
    }
}

__device__ __forceinline__ void sts_chunk64(
    char* sAh_, char* sAl_, char* sBh_, char* sBl_,
    const ChunkRegs& cr, int tid)
{
#pragma unroll
    for (int j = 0; j < 4; j++) {
        int i = tid + j * 256, r = i >> 3, c = i & 7;
        *(uint4*)(sAh_ + r * PITCH + c * 16) = cr.vAh[j];
        *(uint4*)(sAl_ + r * PITCH + c * 16) = cr.vAl[j];
        *(uint4*)(sBh_ + r * PITCH + c * 16) = cr.vBh[j];
        *(uint4*)(sBl_ + r * PITCH + c * 16) = cr.vBl[j];
    }
}

// ---- Fused-kernel KV staging (K 64x64 hi/lo bf16 + V 64x64 fp16) -----------
struct KVRegs {
    uint4 kh[2], kl[2], vv[2];
};

__device__ __forceinline__ void ldg_kv64(
    KVRegs& kr,
    const __nv_bfloat16* gKh, const __nv_bfloat16* gKl,
    const __half* gV, int tid)
{
#pragma unroll
    for (int j = 0; j < 2; j++) {
        int i = tid + j * 256, r = i >> 3, c = i & 7;
        kr.kh[j] = *((const uint4*)(gKh + (size_t)r * DH) + c);
        kr.kl[j] = *((const uint4*)(gKl + (size_t)r * DH) + c);
        kr.vv[j] = *((const uint4*)(gV + (size_t)r * N_) + c);
    }
}

__device__ __forceinline__ void sts_kv64(char* stage, const KVRegs& kr, int tid)
{
#pragma unroll
    for (int j = 0; j < 2; j++) {
        int i = tid + j * 256, r = i >> 3, c = i & 7;
        *(uint4*)(stage + 0 * TILE_K64 + r * PITCH + c * 16) = kr.kh[j];
        *(uint4*)(stage + 1 * TILE_K64 + r * PITCH + c * 16) = kr.kl[j];
        *(uint4*)(stage + 2 * TILE_K64 + r * PITCH + c * 16) = kr.vv[j];
    }
}

// One chunk of the hi/lo-compensated bf16 MMA (3 products, KS K-slices).
template <int MI, int NI, int KS, int PA, int PB>
__device__ __forceinline__ void mma_tiles(
    float (&acc)[MI][NI][4],
    uint32_t sAh, uint32_t sAl, uint32_t sBh, uint32_t sBl,
    int wm0, int wn0, int lane)
{
#pragma unroll
    for (int ks = 0; ks < KS; ks++) {
        uint32_t ah[MI][4], al[MI][4];
#pragma unroll
        for (int mi = 0; mi < MI; mi++) {
            ldm_x4<PA>(ah[mi], sAh, wm0 + mi * 16, ks * 2, lane);
            ldm_x4<PA>(al[mi], sAl, wm0 + mi * 16, ks * 2, lane);
        }
#pragma unroll
        for (int nj = 0; nj < NI / 2; nj++) {
            uint32_t bh[4], bl[4];
            ldm_x4<PB>(bh, sBh, wn0 + nj * 16, ks * 2, lane);
            ldm_x4<PB>(bl, sBl, wn0 + nj * 16, ks * 2, lane);
#pragma unroll
            for (int mi = 0; mi < MI; mi++) {
                mma_bf16(acc[mi][nj * 2],     ah[mi], bh[0], bh[2]);
                mma_bf16(acc[mi][nj * 2],     al[mi], bh[0], bh[2]);
                mma_bf16(acc[mi][nj * 2],     ah[mi], bl[0], bl[2]);
                mma_bf16(acc[mi][nj * 2 + 1], ah[mi], bh[1], bh[3]);
                mma_bf16(acc[mi][nj * 2 + 1], al[mi], bh[1], bh[3]);
                mma_bf16(acc[mi][nj * 2 + 1], ah[mi], bl[1], bl[3]);
            }
        }
    }
}

// ---------------------------------------------------------------------------
// Preprocessing kernels
// ---------------------------------------------------------------------------
__global__ __launch_bounds__(256) void conv_x_kernel(const float* __restrict__ x)
{
    size_t i = ((size_t)blockIdx.x * 256 + threadIdx.x) * 8;
    float4 a = *(const float4*)(x + i);
    float4 b = *(const float4*)(x + i + 4);
    float v[8] = {a.x, a.y, a.z, a.w, b.x, b.y, b.z, b.w};
    __align__(16) __nv_bfloat16 h[8], l[8];
#pragma unroll
    for (int j = 0; j < 8; j++) bsplit(v[j], h[j], l[j]);
    *(uint4*)(g_xh + i) = *(uint4*)h;
    *(uint4*)(g_xl + i) = *(uint4*)l;
}

__global__ __launch_bounds__(256) void w_trans_kernel(
    const float* __restrict__ Wq, const float* __restrict__ Wk,
    const float* __restrict__ Wv, const float* __restrict__ Wo)
{
    const float* W = (blockIdx.z == 0) ? Wq : (blockIdx.z == 1) ? Wk
                   : (blockIdx.z == 2) ? Wv : Wo;
    __shared__ float t[32][33];
    int tx = threadIdx.x, ty = threadIdx.y;      // (32, 8)
    int n0 = blockIdx.x * 32, k0 = blockIdx.y * 32;
#pragma unroll
    for (int i = 0; i < 32; i += 8)
        t[ty + i][tx] = W[(size_t)(k0 + ty + i) * INNER_ + n0 + tx];
    __syncthreads();
    __nv_bfloat16* wh = g_wth + (size_t)blockIdx.z * QD * INNER_;
    __nv_bfloat16* wl = g_wtl + (size_t)blockIdx.z * QD * INNER_;
#pragma unroll
    for (int i = 0; i < 32; i += 8) {
        int n = n0 + ty + i, k = k0 + tx;
        __nv_bfloat16 h, l;
        bsplit(t[tx][ty + i], h, l);
        wh[(size_t)n * QD + k] = h;
        wl[(size_t)n * QD + k] = l;
    }
}

__global__ __launch_bounds__(256) void mask_pack_kernel(const int* __restrict__ m)
{
    size_t w = (size_t)blockIdx.x * 256 + threadIdx.x;
    const int* src = m + w * 32;
    uint32_t bits = 0;
#pragma unroll
    for (int j = 0; j < 32; j++) bits |= (uint32_t)(src[j] > 0) << j;
    g_mb[w] = bits;
}

// ---------------------------------------------------------------------------
// Kernel A: QKV projection.  BM=BN=128, BK=64, double-buffered smem,
// one __syncthreads per chunk.  No register state crosses any barrier.
// ---------------------------------------------------------------------------
__global__ __launch_bounds__(256, 1) void qkv_hmma()
{
    extern __shared__ __align__(16) char smem[];

    const int tid = threadIdx.x, lane = tid & 31, w = tid >> 5;
    const int wm0 = (w >> 2) * 64, wn0 = (w & 3) * 32;
    const int z = blockIdx.z;
    const int row0 = blockIdx.y * 128, col0 = blockIdx.x * 128;

    const __nv_bfloat16* wh = g_wth + (size_t)z * QD * INNER_;
    const __nv_bfloat16* wl = g_wtl + (size_t)z * QD * INNER_;
    const __nv_bfloat16* Ah = g_xh + (size_t)row0 * QD;
    const __nv_bfloat16* Al = g_xl + (size_t)row0 * QD;
    const __nv_bfloat16* Bh = wh + (size_t)col0 * QD;
    const __nv_bfloat16* Bl = wl + (size_t)col0 * QD;

    float acc[4][4][4] = {};

    // Preamble: fill stage 0 (ldg+sts inside one interval).
    {
        ChunkRegs cr;
        ldg_chunk64(cr, Ah, Al, Bh, Bl, QD, QD, tid);
        char* st = smem;
        sts_chunk64(st, st + TILE_A, st + 2 * TILE_A, st + 3 * TILE_A, cr, tid);
    }
    __syncthreads();

    for (int c = 0; c < 16; c++) {
        ChunkRegs cr;
        const bool more = (c + 1 < 16);
        if (more) {
            int k0 = (c + 1) * 64;
            ldg_chunk64(cr, Ah + k0, Al + k0, Bh + k0, Bl + k0, QD, QD, tid);
        }
        char* cur = smem + (c & 1) * STG_GEMM;
        uint32_t u = smem_to_u32(cur);
        mma_tiles<4, 4, 4, PITCH, PITCH>(acc, u, u + TILE_A, u + 2 * TILE_A,
                                         u + 3 * TILE_A, wm0, wn0, lane);
        if (more) {
            char* nxt = smem + ((c + 1) & 1) * STG_GEMM;
            sts_chunk64(nxt, nxt + TILE_A, nxt + 2 * TILE_A, nxt + 3 * TILE_A,
                        cr, tid);
        }
        __syncthreads();
    }

    if (z < 2) {
        __nv_bfloat16* dh_ = (z == 0) ? g_qh : g_kh;
        __nv_bfloat16* dl_ = (z == 0) ? g_ql : g_kl;
#pragma unroll
        for (int mi = 0; mi < 4; mi++)
#pragma unroll
            for (int h2 = 0; h2 < 2; h2++) {
                int m = row0 + wm0 + mi * 16 + (lane >> 2) + h2 * 8;
                int b = m >> 11, n = m & (N_ - 1);
#pragma unroll
                for (int ni = 0; ni < 4; ni++) {
                    int c = col0 + wn0 + ni * 8 + 2 * (lane & 3);
                    int hh = c >> 6, dd = c & 63;
                    __nv_bfloat16 h0, l0, h1, l1;
                    bsplit(acc[mi][ni][h2 * 2 + 0], h0, l0);
                    bsplit(acc[mi][ni][h2 * 2 + 1], h1, l1);
                    size_t off = ((size_t)(b * H_ + hh) * N_ + n) * DH + dd;
                    __nv_bfloat162 ph; ph.x = h0; ph.y = h1;
                    __nv_bfloat162 pl; pl.x = l0; pl.y = l1;
                    *(__nv_bfloat162*)(dh_ + off) = ph;
                    *(__nv_bfloat162*)(dl_ + off) = pl;
                }
            }
    } else {
        // V: single fp16 value, transposed [bh][d][n]
#pragma unroll
        for (int mi = 0; mi < 4; mi++)
#pragma unroll
            for (int h2 = 0; h2 < 2; h2++) {
                int m = row0 + wm0 + mi * 16 + (lane >> 2) + h2 * 8;
                int b = m >> 11, n = m & (N_ - 1);
#pragma unroll
                for (int ni = 0; ni < 4; ni++)
#pragma unroll
                    for (int c01 = 0; c01 < 2; c01++) {
                        int c = col0 + wn0 + ni * 8 + 2 * (lane & 3) + c01;
                        int hh = c >> 6, dd = c & 63;
                        size_t off = ((size_t)(b * H_ + hh) * DH + dd) * N_ + n;
                        g_vt[off] = __float2half(acc[mi][ni][h2 * 2 + c01]);
                    }
            }
    }
}

// ---------------------------------------------------------------------------
// Kernel B (fused): scores + mask + exp + PV, flash-style, KV double-buffered.
// Key-block 64.  P/V fp16 single-limb O-MMA; S bf16 hi/lo 3-product.
// 2 CTAs/SM.  Per iter: [ldg KV(j+1) | S-mma(stage j) | exp->P | sts KV(j+1)]
// sync  [O-mma(P, V stage j)] sync.
// ---------------------------------------------------------------------------
__global__ __launch_bounds__(256, 2) void attn_fused()
{
    extern __shared__ __align__(16) char smem[];
    __shared__ float psum_s[128];

    char* sQh = smem + OFF_QH;  char* sQl = smem + OFF_QL;
    char* sP  = smem + OFF_P;

    const int tid = threadIdx.x, lane = tid & 31, w = tid >> 5;
    const int wmS = (w >> 1) * 32, wnS = (w & 1) * 32;
    const int wmO = (w >> 1) * 32, wnO = (w & 1) * 32;
    const int z = blockIdx.y, b = z >> 4, hh = z & 15;
    const int row0 = blockIdx.x * 128;

    const size_t qb = (size_t)z * N_ * DH;
    const size_t vb = (size_t)z * DH * N_;

    const uint32_t uQh = smem_to_u32(sQh), uQl = smem_to_u32(sQl);
    const uint32_t uP  = smem_to_u32(sP);

    // Preamble: Q block + KV stage 0 + psum init.
    {
        uint4 qh[4], ql[4];
#pragma unroll
        for (int j = 0; j < 4; j++) {
            int i = tid + j * 256, r = i >> 3, c = i & 7;
            qh[j] = *((const uint4*)(g_qh + qb + (size_t)(row0 + r) * DH) + c);
            ql[j] = *((const uint4*)(g_ql + qb + (size_t)(row0 + r) * DH) + c);
        }
#pragma unroll
        for (int j = 0; j < 4; j++) {
            int i = tid + j * 256, r = i >> 3, c = i & 7;
            *(uint4*)(sQh + r * PITCH + c * 16) = qh[j];
            *(uint4*)(sQl + r * PITCH + c * 16) = ql[j];
        }
        KVRegs kr;
        ldg_kv64(kr, g_kh + qb, g_kl + qb, g_vt + vb, tid);
        sts_kv64(smem + OFF_KV, kr, tid);
    }
    if (tid < 128) psum_s[tid] = 0.f;
    __syncthreads();

    float accO[2][4][4] = {};

    for (int j = 0; j < N_ / 64; j++) {
        // ---- interval A: ldg KV(j+1), S-mma(stage j), exp->P, sts KV(j+1)
        KVRegs kr;
        const bool more = (j + 1 < N_ / 64);
        if (more)
            ldg_kv64(kr,
                     g_kh + qb + (size_t)((j + 1) * 64) * DH,
                     g_kl + qb + (size_t)((j + 1) * 64) * DH,
                     g_vt + vb + (j + 1) * 64, tid);

        char* cur = smem + OFF_KV + (j & 1) * STG_KV;
        const uint32_t uKh = smem_to_u32(cur);
        const uint32_t uKl = uKh + TILE_K64;
        const uint32_t uV  = uKh + 2 * TILE_K64;

        float accS[2][4][4] = {};
        mma_tiles<2, 4, 4, PITCH, PITCH>(accS, uQh, uQl, uKh, uKl, wmS, wnS, lane);

        const int mword = (j * 64 + wnS) >> 5;
#pragma unroll
        for (int mi = 0; mi < 2; mi++)
#pragma unroll
            for (int h2 = 0; h2 < 2; h2++) {
                int rloc = wmS + mi * 16 + (lane >> 2) + h2 * 8;
                int i = row0 + rloc;
                uint32_t mw = g_mb[((size_t)b * N_ + i) * (N_ / 32) + mword];
                float rs = 0.f;
#pragma unroll
                for (int ni = 0; ni < 4; ni++) {
                    int bit = ni * 8 + 2 * (lane & 3);
                    float e0 = 0.f, e1 = 0.f;
                    if ((mw >> bit) & 1u)
                        e0 = __expf(accS[mi][ni][h2 * 2 + 0] * 0.125f);
                    if ((mw >> (bit + 1)) & 1u)
                        e1 = __expf(accS[mi][ni][h2 * 2 + 1] * 0.125f);
                    rs += e0 + e1;
                    int col = wnS + ni * 8 + 2 * (lane & 3);
                    *(__half2*)(sP + rloc * PITCH + col * 2) =
                        __floats2half2_rn(e0, e1);
                }
                rs += __shfl_xor_sync(0xFFFFFFFF, rs, 1);
                rs += __shfl_xor_sync(0xFFFFFFFF, rs, 2);
                if ((lane & 3) == 0) atomicAdd(&psum_s[rloc], rs);
            }

        if (more) sts_kv64(smem + OFF_KV + ((j + 1) & 1) * STG_KV, kr, tid);
        __syncthreads();   // P + KV(j+1) visible

        // ---- interval B: O += P @ V (stage j)
#pragma unroll
        for (int ks = 0; ks < 4; ks++) {
            uint32_t ap[2][4];
#pragma unroll
            for (int mi = 0; mi < 2; mi++)
                ldm_x4<PITCH>(ap[mi], uP, wmO + mi * 16, ks * 2, lane);
#pragma unroll
            for (int nj = 0; nj < 2; nj++) {
                uint32_t bv[4];
                ldm_x4<PITCH>(bv, uV, wnO + nj * 16, ks * 2, lane);
#pragma unroll
                for (int mi = 0; mi < 2; mi++) {
                    mma_f16(accO[mi][nj * 2],     ap[mi], bv[0], bv[2]);
                    mma_f16(accO[mi][nj * 2 + 1], ap[mi], bv[1], bv[3]);
                }
            }
        }
        __syncthreads();   // protect sP / V-stage reuse next iter
    }

    // Normalize by row sum and write [b*N+i][h*64+c] hi/lo
#pragma unroll
    for (int mi = 0; mi < 2; mi++)
#pragma unroll
        for (int h2 = 0; h2 < 2; h2++) {
            int rloc = wmO + mi * 16 + (lane >> 2) + h2 * 8;
            int i = row0 + rloc;
            float inv = 1.f / psum_s[rloc];
#pragma unroll
            for (int ni = 0; ni < 4; ni++) {
                int c = wnO + ni * 8 + 2 * (lane & 3);
                __nv_bfloat16 h0, l0, h1, l1;
                bsplit(accO[mi][ni][h2 * 2 + 0] * inv, h0, l0);
                bsplit(accO[mi][ni][h2 * 2 + 1] * inv, h1, l1);
                size_t off = ((size_t)(b * N_ + i)) * INNER_ + hh * 64 + c;
                __nv_bfloat162 ph; ph.x = h0; ph.y = h1;
                __nv_bfloat162 pl; pl.x = l0; pl.y = l1;
                *(__nv_bfloat162*)(g_ath + off) = ph;
                *(__nv_bfloat162*)(g_atl + off) = pl;
            }
        }
}

// ---------------------------------------------------------------------------
// Kernel C: output projection + bias -> d_out (fp32).  Single-buffer
// (validated R13 structure), 16 chunks of 64, 2 CTAs/SM.
// ---------------------------------------------------------------------------
__global__ __launch_bounds__(256, 2) void outproj_hmma(
    const float* __restrict__ bo, float* __restrict__ out)
{
    extern __shared__ __align__(16) char smem[];
    char* sAh = smem;
    char* sAl = smem + TILE_A;
    char* sBh = smem + 2 * TILE_A;
    char* sBl = smem + 3 * TILE_A;

    const int tid = threadIdx.x, lane = tid & 31, w = tid >> 5;
    const int wm0 = (w >> 2) * 64, wn0 = (w & 3) * 32;
    const int row0 = blockIdx.y * 128, col0 = blockIdx.x * 128;

    const __nv_bfloat16* wh = g_wth + (size_t)3 * QD * INNER_;
    const __nv_bfloat16* wl = g_wtl + (size_t)3 * QD * INNER_;

    const uint32_t uAh = smem_to_u32(sAh), uAl = smem_to_u32(sAl);
    const uint32_t uBh = smem_to_u32(sBh), uBl = smem_to_u32(sBl);

    float acc[4][4][4] = {};

    for (int k0 = 0; k0 < INNER_; k0 += 64) {
        ChunkRegs cr;
        ldg_chunk64(cr,
                    g_ath + (size_t)row0 * INNER_ + k0,
                    g_atl + (size_t)row0 * INNER_ + k0,
                    wh + (size_t)col0 * QD + k0,
                    wl + (size_t)col0 * QD + k0,
                    INNER_, QD, tid);
        sts_chunk64(sAh, sAl, sBh, sBl, cr, tid);
        __syncthreads();
        mma_tiles<4, 4, 4, PITCH, PITCH>(acc, uAh, uAl, uBh, uBl, wm0, wn0, lane);
        __syncthreads();
    }

#pragma unroll
    for (int mi = 0; mi < 4; mi++)
#pragma unroll
        for (int h2 = 0; h2 < 2; h2++) {
            int m = row0 + wm0 + mi * 16 + (lane >> 2) + h2 * 8;
#pragma unroll
            for (int ni = 0; ni < 4; ni++) {
                int c = col0 + wn0 + ni * 8 + 2 * (lane & 3);
                float2 o;
                o.x = acc[mi][ni][h2 * 2 + 0] + __ldg(bo + c + 0);
                o.y = acc[mi][ni][h2 * 2 + 1] + __ldg(bo + c + 1);
                *(float2*)(out + (size_t)m * QD + c) = o;
            }
        }
}

// ---------------------------------------------------------------------------
// Launch
// ---------------------------------------------------------------------------
extern "C" void kernel_launch(void* const* d_in, const int* in_sizes, int n_in,
                              void* d_out, int out_size)
{
    const float* x     = (const float*)d_in[0];
    const int*   masks = (const int*)  d_in[1];
    const float* Wq    = (const float*)d_in[2];
    const float* Wk    = (const float*)d_in[3];
    const float* Wv    = (const float*)d_in[4];
    const float* Wo    = (const float*)d_in[5];
    const float* bo    = (const float*)d_in[6];
    float* out = (float*)d_out;
    (void)in_sizes; (void)n_in; (void)out_size;

    // Idempotent, called every launch (no static guards).
    cudaFuncSetAttribute(qkv_hmma,     cudaFuncAttributeMaxDynamicSharedMemorySize, SM_QKV);
    cudaFuncSetAttribute(attn_fused,   cudaFuncAttributeMaxDynamicSharedMemorySize, SM_FUSED);
    cudaFuncSetAttribute(outproj_hmma, cudaFuncAttributeMaxDynamicSharedMemorySize, SM_OUT);

    // Preprocessing
    conv_x_kernel<<<(ROWS * QD) / (256 * 8), 256>>>(x);
    w_trans_kernel<<<dim3(32, 32, 4), dim3(32, 8)>>>(Wq, Wk, Wv, Wo);
    mask_pack_kernel<<<(B_ * N_ * (N_ / 32)) / 256, 256>>>(masks);

    // Main pipeline
    qkv_hmma<<<dim3(INNER_ / 128, ROWS / 128, 3), 256, SM_QKV>>>();
    attn_fused<<<dim3(N_ / 128, BH), 256, SM_FUSED>>>();
    outproj_hmma<<<dim3(QD / 128, ROWS / 128), 256, SM_OUT>>>(bo, out);
}